// round 3
// baseline (speedup 1.0000x reference)
#include <cuda_runtime.h>
#include <cuda_bf16.h>
#include <cstddef>

#define NUM_CLS 19
#define NCH     64
#define HW      (512*512)
#define NBATCH  8
#define NPIX    (NBATCH*HW)          // 2,097,152 pixels
#define CHUNK   8192                 // pixels staged per block (divides HW)
#define CHUNKS_PER_IMG (HW/CHUNK)    // 32
#define NCHUNKS (NPIX/CHUNK)         // 256
#define WARPS   16                   // channels per block
#define BLOCK   (WARPS*32)           // 512 threads
#define GROUPS  (NCH/WARPS)          // 4 channel groups

__device__ float         g_sums[NUM_CLS * NCH];
__device__ float         g_counts[NUM_CLS];
__device__ unsigned char g_cls[NPIX];             // 2 MB label scratch (u8)

// ---------------------------------------------------------------------------
// Kernel 0: zero the global scratch (must run each graph replay)
// ---------------------------------------------------------------------------
__global__ void zero_kernel() {
    int tid = threadIdx.x;
    for (int i = tid; i < NUM_CLS * NCH; i += blockDim.x) g_sums[i] = 0.f;
    if (tid < NUM_CLS) g_counts[tid] = 0.f;
}

// ---------------------------------------------------------------------------
// Kernel 1: compress labels int32 -> uint8 once, and count classes.
// (JAX x64 is disabled by default, so the "int64" targets are int32 on disk.)
// ---------------------------------------------------------------------------
__global__ __launch_bounds__(512) void prep_kernel(
    const int* __restrict__ tgt)
{
    __shared__ int cnt[NUM_CLS];
    const int tid = threadIdx.x;
    if (tid < NUM_CLS) cnt[tid] = 0;
    __syncthreads();

    // int4 = 4 labels per load; NPIX/4 = 524,288 vectors.
    const int4* __restrict__ t4 = (const int4*)tgt;
    const int stride = gridDim.x * blockDim.x;
    for (int i = blockIdx.x * blockDim.x + tid; i < NPIX / 4; i += stride) {
        int4 v = t4[i];
        uchar4 q = make_uchar4((unsigned char)v.x, (unsigned char)v.y,
                               (unsigned char)v.z, (unsigned char)v.w);
        ((uchar4*)g_cls)[i] = q;
        atomicAdd(&cnt[v.x], 1);
        atomicAdd(&cnt[v.y], 1);
        atomicAdd(&cnt[v.z], 1);
        atomicAdd(&cnt[v.w], 1);
    }
    __syncthreads();
    if (tid < NUM_CLS) atomicAdd(&g_counts[tid], (float)cnt[tid]);
}

// ---------------------------------------------------------------------------
// Kernel 2: per-class per-channel scatter-sum.
//   blockIdx.x : pixel chunk (256)    blockIdx.y : channel group (4)
//   warp w handles channel c = group*16 + w over the whole chunk.
//   bins[cls][tid] is thread-private -> no atomics, bank-conflict-free
//   (bank = tid % 32 independent of cls since 512 % 32 == 0).
// ---------------------------------------------------------------------------
__global__ __launch_bounds__(BLOCK) void accum_kernel(
    const float* __restrict__ in)
{
    __shared__ float bins[NUM_CLS][BLOCK];          // 38,912 B
    __shared__ unsigned char cls[CHUNK];            //  8,192 B

    const int tid  = threadIdx.x;
    const int warp = tid >> 5;
    const int lane = tid & 31;
    const int chunk = blockIdx.x;
    const int group = blockIdx.y;
    const int b   = chunk / CHUNKS_PER_IMG;
    const int hw0 = (chunk % CHUNKS_PER_IMG) * CHUNK;

#pragma unroll
    for (int k = 0; k < NUM_CLS; k++) bins[k][tid] = 0.f;

    // Stage compressed labels for this chunk (uint4 = 16 labels/thread).
    {
        const uint4* __restrict__ src8 =
            (const uint4*)(g_cls + (size_t)b * HW + hw0);
        ((uint4*)cls)[tid] = src8[tid];             // CHUNK/16 == BLOCK
    }
    __syncthreads();

    // Main streaming loop: warp = one channel, float4 + uchar4 per lane.
    const int c = group * WARPS + warp;
    const float4* __restrict__ src = (const float4*)(
        in + (size_t)b * NCH * HW + (size_t)c * HW + hw0);
    const uchar4* __restrict__ cls4 = (const uchar4*)cls;

#pragma unroll 4
    for (int i = lane; i < CHUNK / 4; i += 32) {
        float4 x = src[i];
        uchar4 q = cls4[i];
        bins[q.x][tid] += x.x;
        bins[q.y][tid] += x.y;
        bins[q.z][tid] += x.z;
        bins[q.w][tid] += x.w;
    }
    __syncthreads();

    // Per-warp reduction over 32 lanes for each class, then global atomics.
#pragma unroll
    for (int k = 0; k < NUM_CLS; k++) {
        float v = bins[k][tid];
#pragma unroll
        for (int o = 16; o > 0; o >>= 1)
            v += __shfl_down_sync(0xffffffffu, v, o);
        if (lane == 0) atomicAdd(&g_sums[k * NCH + c], v);
    }
}

// ---------------------------------------------------------------------------
// Kernel 3: centroids -> cosine matrix -> loss (1 block, tiny)
// ---------------------------------------------------------------------------
__global__ __launch_bounds__(512) void finalize_kernel(float* __restrict__ out)
{
    __shared__ float cn[NUM_CLS][NCH];
    __shared__ float nrm[NUM_CLS];
    __shared__ float rbuf[16];

    const int tid  = threadIdx.x;
    const int warp = tid >> 5;
    const int lane = tid & 31;

    for (int i = tid; i < NUM_CLS * NCH; i += blockDim.x) {
        int k = i / NCH;
        cn[k][i % NCH] = g_sums[i] / fmaxf(g_counts[k], 1.f);
    }
    __syncthreads();

    if (tid < NUM_CLS) {
        float s = 0.f;
#pragma unroll
        for (int c = 0; c < NCH; c++) s += cn[tid][c] * cn[tid][c];
        nrm[tid] = fmaxf(sqrtf(s), 1e-8f);
    }
    __syncthreads();

    for (int i = tid; i < NUM_CLS * NCH; i += blockDim.x)
        cn[i / NCH][i % NCH] /= nrm[i / NCH];
    __syncthreads();

    float acc = 0.f;
    for (int p = tid; p < NUM_CLS * NUM_CLS; p += blockDim.x) {
        int i = p / NUM_CLS, j = p % NUM_CLS;
        float d = 0.f;
#pragma unroll
        for (int c = 0; c < NCH; c++) d += cn[i][c] * cn[j][c];
        acc += (i == j) ? (1.f - d) : fmaxf(d, 0.f);
    }
#pragma unroll
    for (int o = 16; o > 0; o >>= 1)
        acc += __shfl_down_sync(0xffffffffu, acc, o);
    if (lane == 0) rbuf[warp] = acc;
    __syncthreads();
    if (warp == 0) {
        float v = (lane < 16) ? rbuf[lane] : 0.f;
#pragma unroll
        for (int o = 8; o > 0; o >>= 1)
            v += __shfl_down_sync(0xffffffffu, v, o);
        if (lane == 0)
            out[0] = v / (float)(NUM_CLS * NUM_CLS * NUM_CLS);
    }
}

// ---------------------------------------------------------------------------
extern "C" void kernel_launch(void* const* d_in, const int* in_sizes, int n_in,
                              void* d_out, int out_size)
{
    const float* inputs  = (const float*)d_in[0];
    const int*   targets = (const int*)d_in[1];
    float*       out     = (float*)d_out;

    zero_kernel<<<1, 1024>>>();
    prep_kernel<<<296, 512>>>(targets);
    accum_kernel<<<dim3(NCHUNKS, GROUPS), BLOCK>>>(inputs);
    finalize_kernel<<<1, 512>>>(out);
}

// round 4
// speedup vs baseline: 1.0056x; 1.0056x over previous
#include <cuda_runtime.h>
#include <cuda_bf16.h>
#include <cstddef>

#define NUM_CLS 19
#define NCH     64
#define HW      (512*512)
#define NBATCH  8
#define NPIX    (NBATCH*HW)          // 2,097,152 pixels
#define CHUNK   8192                 // pixels per block
#define CHUNKS_PER_IMG (HW/CHUNK)    // 32
#define NCHUNKS (NPIX/CHUNK)         // 256 = grid size (single wave)
#define WARPS   16
#define BLOCK   (WARPS*32)           // 512 threads
#define GROUPS  (NCH/WARPS)          // 4 channel passes per block

__device__ float        g_sums[NUM_CLS * NCH];
__device__ float        g_counts[NUM_CLS];
__device__ unsigned int g_ticket;

// ---------------------------------------------------------------------------
// One fused kernel: scatter-sum + class counts + last-block finalize.
// bins[cls][tid] is thread-private -> no atomics, bank-conflict-free
// (bank = tid % 32 independent of cls since 512 % 32 == 0).
// g_sums/g_counts/g_ticket are zero at module load and reset by the last
// block every run -> deterministic across graph replays.
// ---------------------------------------------------------------------------
__global__ __launch_bounds__(BLOCK) void fused_kernel(
    const float* __restrict__ in, const int* __restrict__ tgt,
    float* __restrict__ out)
{
    __shared__ float bins[NUM_CLS][BLOCK];          // 38,912 B
    __shared__ unsigned char cls[CHUNK];            //  8,192 B
    __shared__ int   cnt[NUM_CLS];
    __shared__ float fcnt[NUM_CLS];
    __shared__ float fnrm[NUM_CLS];
    __shared__ float rbuf[WARPS];
    __shared__ int   sh_last;

    const int tid  = threadIdx.x;
    const int warp = tid >> 5;
    const int lane = tid & 31;
    const int chunk = blockIdx.x;
    const int b   = chunk / CHUNKS_PER_IMG;
    const int hw0 = (chunk % CHUNKS_PER_IMG) * CHUNK;

#pragma unroll
    for (int k = 0; k < NUM_CLS; k++) bins[k][tid] = 0.f;
    if (tid < NUM_CLS) cnt[tid] = 0;
    __syncthreads();

    // Stage labels (int32 -> u8 in smem) and count them (once per pixel).
    {
        const int4* __restrict__ t4 = (const int4*)(tgt + (size_t)b * HW + hw0);
        uchar4* c4 = (uchar4*)cls;
#pragma unroll
        for (int i = tid; i < CHUNK / 4; i += BLOCK) {
            int4 v = t4[i];
            c4[i] = make_uchar4((unsigned char)v.x, (unsigned char)v.y,
                                (unsigned char)v.z, (unsigned char)v.w);
            atomicAdd(&cnt[v.x], 1); atomicAdd(&cnt[v.y], 1);
            atomicAdd(&cnt[v.z], 1); atomicAdd(&cnt[v.w], 1);
        }
    }
    __syncthreads();
    if (tid < NUM_CLS) atomicAdd(&g_counts[tid], (float)cnt[tid]);

    // Stream features: 4 passes, warp = one channel per pass.
    const uchar4* __restrict__ cls4 = (const uchar4*)cls;
    for (int g = 0; g < GROUPS; g++) {
        const int c = g * WARPS + warp;
        const float4* __restrict__ src = (const float4*)(
            in + ((size_t)b * NCH + c) * HW + hw0);
#pragma unroll 4
        for (int i = lane; i < CHUNK / 4; i += 32) {
            float4 x = __ldcs(src + i);
            uchar4 q = cls4[i];
            bins[q.x][tid] += x.x;
            bins[q.y][tid] += x.y;
            bins[q.z][tid] += x.z;
            bins[q.w][tid] += x.w;
        }
        // Flush this channel: warp-reduce each class, re-zero bins.
#pragma unroll
        for (int k = 0; k < NUM_CLS; k++) {
            float v = bins[k][tid];
            bins[k][tid] = 0.f;
#pragma unroll
            for (int o = 16; o > 0; o >>= 1)
                v += __shfl_down_sync(0xffffffffu, v, o);
            if (lane == 0) atomicAdd(&g_sums[k * NCH + c], v);
        }
    }

    // Ticket: last block to arrive does the finalize.
    __threadfence();
    __syncthreads();
    if (tid == 0)
        sh_last = (atomicAdd(&g_ticket, 1u) == (unsigned)(NCHUNKS - 1));
    __syncthreads();
    if (!sh_last) return;

    // ---------------- finalize (last block only) ----------------
    __threadfence();
    float* cen = &bins[0][0];                       // reuse smem: 1216 floats

    if (tid < NUM_CLS) fcnt[tid] = atomicExch(&g_counts[tid], 0.f);
    __syncthreads();
    for (int i = tid; i < NUM_CLS * NCH; i += BLOCK)
        cen[i] = atomicExch(&g_sums[i], 0.f) / fmaxf(fcnt[i >> 6], 1.f);
    __syncthreads();

    if (tid < NUM_CLS) {
        float s = 0.f;
#pragma unroll
        for (int c = 0; c < NCH; c++) {
            float v = cen[tid * NCH + c];
            s += v * v;
        }
        fnrm[tid] = fmaxf(sqrtf(s), 1e-8f);
    }
    __syncthreads();

    float acc = 0.f;
    if (tid < NUM_CLS * NUM_CLS) {
        int i = tid / NUM_CLS, j = tid % NUM_CLS;
        float d = 0.f;
#pragma unroll
        for (int c = 0; c < NCH; c++)
            d += cen[i * NCH + c] * cen[j * NCH + c];
        d /= (fnrm[i] * fnrm[j]);
        acc = (i == j) ? (1.f - d) : fmaxf(d, 0.f);
    }
#pragma unroll
    for (int o = 16; o > 0; o >>= 1)
        acc += __shfl_down_sync(0xffffffffu, acc, o);
    if (lane == 0) rbuf[warp] = acc;
    __syncthreads();
    if (warp == 0) {
        float v = (lane < WARPS) ? rbuf[lane] : 0.f;
#pragma unroll
        for (int o = 8; o > 0; o >>= 1)
            v += __shfl_down_sync(0xffffffffu, v, o);
        if (lane == 0) {
            out[0] = v / (float)(NUM_CLS * NUM_CLS * NUM_CLS);
            g_ticket = 0u;                          // reset for next replay
        }
    }
}

// ---------------------------------------------------------------------------
extern "C" void kernel_launch(void* const* d_in, const int* in_sizes, int n_in,
                              void* d_out, int out_size)
{
    const float* inputs  = (const float*)d_in[0];
    const int*   targets = (const int*)d_in[1];
    float*       out     = (float*)d_out;

    fused_kernel<<<NCHUNKS, BLOCK>>>(inputs, targets, out);
}